// round 1
// baseline (speedup 1.0000x reference)
#include <cuda_runtime.h>
#include <math.h>

#define BATCH 32
#define SEQT  512
#define IND   512
#define UNITS 1024
#define GDIM  4096              // 4*UNITS
#define MROWS (BATCH*SEQT)      // 16384

// Scratch (device globals — no runtime allocation allowed)
__device__ float g_xg[(size_t)SEQT * BATCH * GDIM];   // [T][B][4U]  256 MB
__device__ float g_WhT[(size_t)GDIM * UNITS];         // [4U][K]      16 MB
__device__ float g_h[2][BATCH * UNITS];               // ping-pong h
__device__ float g_c[BATCH * UNITS];                  // cell state

// ---------------------------------------------------------------------------
// Transpose Wh [K=1024][4096] -> WhT [4096][1024] so the recurrent GEMM can
// use float4 loads along K.
// ---------------------------------------------------------------------------
__global__ void k_transpose_wh(const float* __restrict__ Wh) {
    __shared__ float tile[32][33];
    int g0 = blockIdx.x * 32;
    int k0 = blockIdx.y * 32;
    int tx = threadIdx.x, ty = threadIdx.y;       // 32 x 8
#pragma unroll
    for (int i = 0; i < 32; i += 8)
        tile[ty + i][tx] = Wh[(size_t)(k0 + ty + i) * GDIM + g0 + tx];
    __syncthreads();
#pragma unroll
    for (int i = 0; i < 32; i += 8)
        g_WhT[(size_t)(g0 + ty + i) * UNITS + k0 + tx] = tile[tx][ty + i];
}

// ---------------------------------------------------------------------------
// State init: h0 = 0, c0 = 1 (reference uses ones for c!)
// ---------------------------------------------------------------------------
__global__ void k_init_state() {
    int i = blockIdx.x * blockDim.x + threadIdx.x;
    if (i < BATCH * UNITS) {
        g_h[0][i] = 0.0f;
        g_c[i]    = 1.0f;
    }
}

// ---------------------------------------------------------------------------
// x-projection: g_xg[t][b][g] = data[b][t][:] @ Wx[:,g] + bias[g]
// Classic 64x64 tile SGEMM, 256 threads, 4x4 register tile.
// ---------------------------------------------------------------------------
__global__ void __launch_bounds__(256) k_xproj(const float* __restrict__ A,
                                               const float* __restrict__ Bw,
                                               const float* __restrict__ bias) {
    __shared__ float As[16][68];   // [k][m], padded (alignment keeps 16B)
    __shared__ float Bs[16][64];   // [k][n]
    int n0 = blockIdx.x * 64;
    int m0 = blockIdx.y * 64;
    int tid = threadIdx.x;
    int tx = tid & 15, ty = tid >> 4;

    float acc[4][4];
#pragma unroll
    for (int i = 0; i < 4; i++)
#pragma unroll
        for (int j = 0; j < 4; j++) acc[i][j] = 0.0f;

    int la_k = tid & 15;   // k in tile
    int la_m = tid >> 4;   // row base (+p*16)
    int lb_n = tid & 63;
    int lb_k = tid >> 6;   // (+p*4)

    for (int k0 = 0; k0 < IND; k0 += 16) {
#pragma unroll
        for (int p = 0; p < 4; p++)
            As[la_k][la_m + p * 16] =
                A[(size_t)(m0 + la_m + p * 16) * IND + k0 + la_k];
#pragma unroll
        for (int p = 0; p < 4; p++)
            Bs[lb_k + p * 4][lb_n] =
                Bw[(size_t)(k0 + lb_k + p * 4) * GDIM + n0 + lb_n];
        __syncthreads();
#pragma unroll
        for (int k = 0; k < 16; k++) {
            float4 ra = *(const float4*)&As[k][ty * 4];
            float4 rb = *(const float4*)&Bs[k][tx * 4];
            float av[4] = {ra.x, ra.y, ra.z, ra.w};
            float bv[4] = {rb.x, rb.y, rb.z, rb.w};
#pragma unroll
            for (int i = 0; i < 4; i++)
#pragma unroll
                for (int j = 0; j < 4; j++) acc[i][j] += av[i] * bv[j];
        }
        __syncthreads();
    }

    // Epilogue: rows m = b*512 + t; the 64-row tile lies within one b.
    int b  = m0 >> 9;
    int tb = (m0 & 511) + ty * 4;
    float4 bb4 = *(const float4*)&bias[n0 + tx * 4];
#pragma unroll
    for (int i = 0; i < 4; i++) {
        float4 v;
        v.x = acc[i][0] + bb4.x;
        v.y = acc[i][1] + bb4.y;
        v.z = acc[i][2] + bb4.z;
        v.w = acc[i][3] + bb4.w;
        *(float4*)&g_xg[(((size_t)(tb + i)) * BATCH + b) * GDIM + n0 + tx * 4] = v;
    }
}

// ---------------------------------------------------------------------------
// One LSTM timestep. grid = 256 blocks (4 u-columns each), 128 threads.
// Thread (b, u) computes the 4 gate dot-products over K=1024, then the
// pointwise update. h read from ping buffer, written to pong buffer.
// ---------------------------------------------------------------------------
#define UB 4
#define KT 256
__global__ void __launch_bounds__(128) k_lstm_step(int t, float* __restrict__ out) {
    __shared__ float hs[BATCH][KT + 4];

    const float* __restrict__ h_in  = g_h[t & 1];
    float* __restrict__       h_out = g_h[(t + 1) & 1];

    int u0 = blockIdx.x * UB;
    int tid = threadIdx.x;
    int b  = tid >> 2;      // 0..31
    int ui = tid & 3;
    int u  = u0 + ui;

    const float* xg = g_xg + ((size_t)t * BATCH + b) * GDIM;
    float ai = xg[u];
    float af = xg[UNITS + u];
    float ag = xg[2 * UNITS + u];
    float ao = xg[3 * UNITS + u];

    const float* __restrict__ wi = g_WhT + (size_t)u * UNITS;
    const float* __restrict__ wf = g_WhT + (size_t)(UNITS + u) * UNITS;
    const float* __restrict__ wg = g_WhT + (size_t)(2 * UNITS + u) * UNITS;
    const float* __restrict__ wo = g_WhT + (size_t)(3 * UNITS + u) * UNITS;

    for (int k0 = 0; k0 < UNITS; k0 += KT) {
        __syncthreads();
        // cooperative load of h tile [32][KT]
        for (int i = tid; i < BATCH * (KT / 4); i += 128) {
            int bb = i >> 6;        // i / (KT/4)
            int kk = i & 63;        // i % (KT/4)
            *(float4*)&hs[bb][kk * 4] =
                *(const float4*)&h_in[bb * UNITS + k0 + kk * 4];
        }
        __syncthreads();
#pragma unroll 8
        for (int k = 0; k < KT; k += 4) {
            float4 hv = *(const float4*)&hs[b][k];
            float4 vi = *(const float4*)&wi[k0 + k];
            float4 vf = *(const float4*)&wf[k0 + k];
            float4 vg = *(const float4*)&wg[k0 + k];
            float4 vo = *(const float4*)&wo[k0 + k];
            ai += hv.x * vi.x + hv.y * vi.y + hv.z * vi.z + hv.w * vi.w;
            af += hv.x * vf.x + hv.y * vf.y + hv.z * vf.z + hv.w * vf.w;
            ag += hv.x * vg.x + hv.y * vg.y + hv.z * vg.z + hv.w * vg.w;
            ao += hv.x * vo.x + hv.y * vo.y + hv.z * vo.z + hv.w * vo.w;
        }
    }

    float ig = 1.0f / (1.0f + expf(-ai));
    float fg = 1.0f / (1.0f + expf(-af));
    float gg = tanhf(ag);
    float og = 1.0f / (1.0f + expf(-ao));

    int cu = b * UNITS + u;
    float c = fg * g_c[cu] + ig * gg;
    g_c[cu] = c;
    float h = og * tanhf(c);
    h_out[cu] = h;
    out[((size_t)b * SEQT + t) * UNITS + u] = h;
}

// ---------------------------------------------------------------------------
// kernel_launch: transpose Wh, init state, x-projection GEMM, then 512
// sequential step launches (graph-capturable; same stream ordering).
// ---------------------------------------------------------------------------
extern "C" void kernel_launch(void* const* d_in, const int* in_sizes, int n_in,
                              void* d_out, int out_size) {
    (void)in_sizes; (void)n_in; (void)out_size;
    const float* data = (const float*)d_in[0];   // [32,512,512]
    const float* Wx   = (const float*)d_in[1];   // [512,4096]
    const float* Wh   = (const float*)d_in[2];   // [1024,4096]
    const float* bias = (const float*)d_in[3];   // [4096]
    float* out = (float*)d_out;                  // [32,512,1024]

    k_transpose_wh<<<dim3(GDIM / 32, UNITS / 32), dim3(32, 8)>>>(Wh);
    k_init_state<<<(BATCH * UNITS + 255) / 256, 256>>>();
    k_xproj<<<dim3(GDIM / 64, MROWS / 64), 256>>>(data, Wx, bias);

    for (int t = 0; t < SEQT; t++)
        k_lstm_step<<<UNITS / UB, 128>>>(t, out);
}

// round 3
// speedup vs baseline: 4.4832x; 4.4832x over previous
#include <cuda_runtime.h>
#include <math.h>

#define BATCH 32
#define SEQT  512
#define IND   512
#define UNITS 1024
#define GDIM  4096              // 4*UNITS
#define MROWS (BATCH*SEQT)      // 16384

#define NS    16                // K-split slices for the recurrent GEMM
#define KSL   (UNITS/NS)        // 64 K per slice
#define NT    128               // n-tile per block
#define NCHUNK (KSL/16)         // 4 smem chunks of 16 k
#define GRID_STEP 512           // blocks in the fused step kernel

// Scratch (device globals — no runtime allocation allowed)
__device__ float g_xg[(size_t)SEQT * BATCH * GDIM];     // [T][B][4U]  256 MB
__device__ float g_hT[2][UNITS * BATCH];                // h transposed [U][B], ping-pong
__device__ float g_c[BATCH * UNITS];                    // cell state [B][U]
__device__ float g_part[(size_t)NS * BATCH * GDIM];     // K-slice partials, 8 MB

// software grid-barrier state (reset every launch by k_init_state)
__device__ unsigned int g_bar_count;
__device__ unsigned int g_bar_release;

__device__ __forceinline__ unsigned int arrive_release_add(unsigned int* p) {
    unsigned int old;
    asm volatile("atom.add.release.gpu.global.u32 %0, [%1], 1;"
                 : "=r"(old) : "l"(p) : "memory");
    return old;
}
__device__ __forceinline__ void store_release(unsigned int* p, unsigned int v) {
    asm volatile("st.release.gpu.global.u32 [%0], %1;" :: "l"(p), "r"(v) : "memory");
}
__device__ __forceinline__ unsigned int ld_acquire(unsigned int* p) {
    unsigned int v;
    asm volatile("ld.acquire.gpu.global.u32 %0, [%1];" : "=r"(v) : "l"(p) : "memory");
    return v;
}

// ---------------------------------------------------------------------------
// State init: hT0 = 0, c0 = 1 (reference inits c to ones); reset barrier.
// ---------------------------------------------------------------------------
__global__ void k_init_state() {
    int i = blockIdx.x * blockDim.x + threadIdx.x;
    if (i < UNITS * BATCH) g_hT[0][i] = 0.0f;
    if (i < BATCH * UNITS) g_c[i] = 1.0f;
    if (i == 0) { g_bar_count = 0; g_bar_release = 0; }
}

// ---------------------------------------------------------------------------
// x-projection: g_xg[t][b][g] = data[b][t][:] @ Wx[:,g] + bias[g]
// ---------------------------------------------------------------------------
__global__ void __launch_bounds__(256) k_xproj(const float* __restrict__ A,
                                               const float* __restrict__ Bw,
                                               const float* __restrict__ bias) {
    __shared__ float As[16][68];
    __shared__ float Bs[16][64];
    int n0 = blockIdx.x * 64;
    int m0 = blockIdx.y * 64;
    int tid = threadIdx.x;
    int tx = tid & 15, ty = tid >> 4;

    float acc[4][4];
#pragma unroll
    for (int i = 0; i < 4; i++)
#pragma unroll
        for (int j = 0; j < 4; j++) acc[i][j] = 0.0f;

    int la_k = tid & 15;
    int la_m = tid >> 4;
    int lb_n = tid & 63;
    int lb_k = tid >> 6;

    for (int k0 = 0; k0 < IND; k0 += 16) {
#pragma unroll
        for (int p = 0; p < 4; p++)
            As[la_k][la_m + p * 16] =
                A[(size_t)(m0 + la_m + p * 16) * IND + k0 + la_k];
#pragma unroll
        for (int p = 0; p < 4; p++)
            Bs[lb_k + p * 4][lb_n] =
                Bw[(size_t)(k0 + lb_k + p * 4) * GDIM + n0 + lb_n];
        __syncthreads();
#pragma unroll
        for (int k = 0; k < 16; k++) {
            float4 ra = *(const float4*)&As[k][ty * 4];
            float4 rb = *(const float4*)&Bs[k][tx * 4];
            float av[4] = {ra.x, ra.y, ra.z, ra.w};
            float bv[4] = {rb.x, rb.y, rb.z, rb.w};
#pragma unroll
            for (int i = 0; i < 4; i++)
#pragma unroll
                for (int j = 0; j < 4; j++) acc[i][j] += av[i] * bv[j];
        }
        __syncthreads();
    }

    int b  = m0 >> 9;
    int tb = (m0 & 511) + ty * 4;
    float4 bb4 = *(const float4*)&bias[n0 + tx * 4];
#pragma unroll
    for (int i = 0; i < 4; i++) {
        float4 v;
        v.x = acc[i][0] + bb4.x;
        v.y = acc[i][1] + bb4.y;
        v.z = acc[i][2] + bb4.z;
        v.w = acc[i][3] + bb4.w;
        *(float4*)&g_xg[(((size_t)(tb + i)) * BATCH + b) * GDIM + n0 + tx * 4] = v;
    }
}

// ---------------------------------------------------------------------------
// Fused LSTM step: phase 1 = K-split recurrent GEMM into g_part, software
// grid barrier, phase 2 = partial reduction + gates + c/h update + stores.
// grid = 512 blocks x 256 threads, all co-resident (launch_bounds(256,4)).
// ---------------------------------------------------------------------------
__global__ void __launch_bounds__(256, 4) k_step(int t, const float* __restrict__ Wh,
                                                 float* __restrict__ out) {
    __shared__ float As[2][16][32];    // [buf][k][b]
    __shared__ float Bs[2][16][NT];    // [buf][k][n]

    const float* __restrict__ hT = g_hT[t & 1];

    int bx = blockIdx.x;
    int n0 = (bx & 31) * NT;
    int s  = bx >> 5;
    int k_base = s * KSL;

    int tid = threadIdx.x;
    int tx = tid & 31;     // n/4
    int ty = tid >> 5;     // b/4 (0..7)

    int ak  = tid >> 3;    // k (only tid<128: 0..15)
    int am4 = tid & 7;     // b/4
    int bk  = tid >> 5;    // 0..7
    int bn4 = tid & 31;    // n/4

    float acc[4][4];
#pragma unroll
    for (int i = 0; i < 4; i++)
#pragma unroll
        for (int j = 0; j < 4; j++) acc[i][j] = 0.0f;

    if (tid < 128)
        *(float4*)&As[0][ak][am4 * 4] =
            *(const float4*)&hT[(k_base + ak) * BATCH + am4 * 4];
#pragma unroll
    for (int p = 0; p < 2; p++)
        *(float4*)&Bs[0][bk + p * 8][bn4 * 4] =
            *(const float4*)&Wh[(size_t)(k_base + bk + p * 8) * GDIM + n0 + bn4 * 4];
    __syncthreads();

#pragma unroll
    for (int c = 0; c < NCHUNK; c++) {
        int cur = c & 1, nxt = cur ^ 1;
        float4 ra;
        float4 rb0, rb1;
        if (c + 1 < NCHUNK) {
            int k0 = k_base + (c + 1) * 16;
            if (tid < 128)
                ra = *(const float4*)&hT[(k0 + ak) * BATCH + am4 * 4];
            rb0 = *(const float4*)&Wh[(size_t)(k0 + bk) * GDIM + n0 + bn4 * 4];
            rb1 = *(const float4*)&Wh[(size_t)(k0 + bk + 8) * GDIM + n0 + bn4 * 4];
        }
#pragma unroll
        for (int k = 0; k < 16; k++) {
            float4 a4 = *(const float4*)&As[cur][k][ty * 4];
            float4 b4 = *(const float4*)&Bs[cur][k][tx * 4];
            float av[4] = {a4.x, a4.y, a4.z, a4.w};
            float bv[4] = {b4.x, b4.y, b4.z, b4.w};
#pragma unroll
            for (int i = 0; i < 4; i++)
#pragma unroll
                for (int j = 0; j < 4; j++) acc[i][j] += av[i] * bv[j];
        }
        if (c + 1 < NCHUNK) {
            if (tid < 128) *(float4*)&As[nxt][ak][am4 * 4] = ra;
            *(float4*)&Bs[nxt][bk][bn4 * 4] = rb0;
            *(float4*)&Bs[nxt][bk + 8][bn4 * 4] = rb1;
        }
        __syncthreads();
    }

    // write partials
    float* pp = g_part + ((size_t)s * BATCH) * GDIM;
#pragma unroll
    for (int i = 0; i < 4; i++) {
        int b = ty * 4 + i;
        float4 v;
        v.x = acc[i][0]; v.y = acc[i][1]; v.z = acc[i][2]; v.w = acc[i][3];
        *(float4*)&pp[(size_t)b * GDIM + n0 + tx * 4] = v;
    }

    // ---- software grid barrier (single use per launch) ----
    __syncthreads();               // all threads' partial stores issued
    if (tid == 0) {
        unsigned int old = arrive_release_add(&g_bar_count);
        if (old == GRID_STEP - 1) {
            g_bar_count = 0;                       // reset for next launch
            store_release(&g_bar_release, (unsigned int)(t + 1));
        } else {
            while (ld_acquire(&g_bar_release) < (unsigned int)(t + 1))
                __nanosleep(64);
        }
    }
    __syncthreads();

    // ---- phase 2: pointwise (64 elements per block) ----
    if (tid < 64) {
        int idx = bx * 64 + tid;          // 0..32767
        int b = idx >> 10;
        int u = idx & 1023;

        const float* xg = g_xg + ((size_t)t * BATCH + b) * GDIM;
        float ai = xg[u];
        float af = xg[UNITS + u];
        float ag = xg[2 * UNITS + u];
        float ao = xg[3 * UNITS + u];

#pragma unroll
        for (int ss = 0; ss < NS; ss++) {
            const float* p = g_part + ((size_t)ss * BATCH + b) * GDIM;
            ai += p[u];
            af += p[UNITS + u];
            ag += p[2 * UNITS + u];
            ao += p[3 * UNITS + u];
        }

        float ig = 1.0f / (1.0f + expf(-ai));
        float fg = 1.0f / (1.0f + expf(-af));
        float gg = tanhf(ag);
        float og = 1.0f / (1.0f + expf(-ao));

        int cu = b * UNITS + u;
        float c = fg * g_c[cu] + ig * gg;
        g_c[cu] = c;
        float h = og * tanhf(c);

        g_hT[(t + 1) & 1][u * BATCH + b] = h;
        out[((size_t)b * SEQT + t) * UNITS + u] = h;
    }
}

// ---------------------------------------------------------------------------
// kernel_launch: 514 graph nodes total (same scale as the passing R1 graph).
// ---------------------------------------------------------------------------
extern "C" void kernel_launch(void* const* d_in, const int* in_sizes, int n_in,
                              void* d_out, int out_size) {
    (void)in_sizes; (void)n_in; (void)out_size;
    const float* data = (const float*)d_in[0];   // [32,512,512]
    const float* Wx   = (const float*)d_in[1];   // [512,4096]
    const float* Wh   = (const float*)d_in[2];   // [1024,4096]
    const float* bias = (const float*)d_in[3];   // [4096]
    float* out = (float*)d_out;                  // [32,512,1024]

    k_init_state<<<(UNITS * BATCH + 255) / 256, 256>>>();
    k_xproj<<<dim3(GDIM / 64, MROWS / 64), 256>>>(data, Wx, bias);

    for (int t = 0; t < SEQT; t++)
        k_step<<<GRID_STEP, 256>>>(t, Wh, out);
}